// round 11
// baseline (speedup 1.0000x reference)
#include <cuda_runtime.h>

#define S 1024
#define G 10
#define F 5
#define BB 8
#define CC 3
#define KW (2*F+1)
#define PX 4          // pixels per thread (x direction), lane-strided
#define TPB 128       // threads per block
#define SPAN (PX*TPB) // 512 output pixels per block row-segment

// Scratch for the smoothed, clipped offset field: (B, 2, G, G)
__device__ float g_smooth_dev[BB * 2 * G * G];

// ---------------------------------------------------------------------------
// Kernel 1: 11x11 edge-padded conv of the 10x10 offset fields + clip.
// ---------------------------------------------------------------------------
__global__ void smooth_kernel(const float* __restrict__ ox,
                              const float* __restrict__ oy,
                              const float* __restrict__ w,
                              const int*   __restrict__ mm_raw)
{
    int   mi = mm_raw[0];
    float max_move = (mi > 0 && mi < 1000000) ? (float)mi : __int_as_float(mi);
    float max_offset = 2.0f * max_move / (float)S;

    __shared__ float sw[KW * KW];
    __shared__ float so[G * G];

    int b  = blockIdx.x >> 1;
    int ch = blockIdx.x & 1;
    const float* o = (ch == 0 ? ox : oy) + b * G * G;

    for (int i = threadIdx.x; i < KW * KW; i += blockDim.x) sw[i] = w[i];
    for (int i = threadIdx.x; i < G * G;   i += blockDim.x) so[i] = o[i];
    __syncthreads();

    for (int idx = threadIdx.x; idx < G * G; idx += blockDim.x) {
        int i = idx / G, j = idx % G;
        float acc = 0.0f;
        #pragma unroll
        for (int ky = 0; ky < KW; ky++) {
            int yy = min(max(i + ky - F, 0), G - 1);
            #pragma unroll
            for (int kx = 0; kx < KW; kx++) {
                int xx = min(max(j + kx - F, 0), G - 1);
                acc += so[yy * G + xx] * sw[ky * KW + kx];
            }
        }
        acc *= max_offset;
        acc = fminf(fmaxf(acc, -max_offset), max_offset);
        g_smooth_dev[(b * 2 + ch) * G * G + idx] = acc;
    }
}

// ---------------------------------------------------------------------------
// Kernel 2: fused upsample + grid build + bilinear grid_sample, 3 channels.
// Two-phase structure: (1) compute weights+offsets for all PX pixels,
// (2) per channel, issue 16 independent LDGs (MLP=16) then accumulate.
// __launch_bounds__(128, 8) gives ptxas a 64-reg budget to hold the batch.
// ---------------------------------------------------------------------------
__global__ __launch_bounds__(TPB, 8)
void deform_kernel(const float* __restrict__ x, float* __restrict__ out)
{
    const int b   = blockIdx.z;
    const int y   = blockIdx.y;
    const int tid = threadIdx.x;

    __shared__ float rowg[2 * G];   // [0..9] = gx row, [10..19] = gy row

    const float scale = (float)G / (float)S;      // exact
    const float hs    = 0.5f * scale - 0.5f;

    // y-direction field interpolation, once per block
    if (tid < 2 * G) {
        int ch = tid / G;
        int j  = tid - ch * G;
        float sy  = fmaxf(fmaf((float)y, scale, hs), 0.0f);
        int   iy0 = min((int)sy, G - 1);
        int   iy1 = min(iy0 + 1, G - 1);
        float wy  = sy - (float)iy0;
        const float* f = g_smooth_dev + (b * 2 + ch) * G * G;
        float a = f[iy0 * G + j];
        float c = f[iy1 * G + j];
        rowg[tid] = fmaf(c - a, wy, a);
    }
    __syncthreads();

    const float* rowgx = rowg;
    const float* rowgy = rowg + G;

    const int   xb  = blockIdx.x * SPAN;              // 0 or 512
    const float pxs = 2.0f / (float)(S - 1);
    const float pyv = fmaf((float)y, pxs, -1.0f);     // identity grid y

    const float* img = x   + (size_t)b * CC * S * S;
    float*       op  = out + (size_t)b * CC * S * S + (size_t)y * S
                           + xb + tid;

    // ---- Phase 1: all PX pixels' weights + offsets ----
    float wgt[PX][4];
    int   off[PX][4];

    #pragma unroll
    for (int p = 0; p < PX; p++) {
        float xf = (float)(xb + p * TPB + tid);

        // field x-lerp from shared row
        float sx = fmaxf(fmaf(xf, scale, hs), 0.0f);
        int   j0 = min((int)sx, G - 1);
        int   j1 = min(j0 + 1, G - 1);
        float wx = sx - (float)j0;
        float ax0 = rowgx[j0], ax1 = rowgx[j1];
        float ay0 = rowgy[j0], ay1 = rowgy[j1];
        float gx = fmaf(ax1 - ax0, wx, ax0);
        float gy = fmaf(ay1 - ay0, wx, ay0);

        // identity grid + clip
        float g0 = fminf(fmaxf(gx + fmaf(xf, pxs, -1.0f), -1.0f), 1.0f);
        float g1 = fminf(fmaxf(gy + pyv, -1.0f), 1.0f);

        // source coords: g*512 + 511.5, in [-0.5, 1023.5]
        float ixf = fmaf(g0, 512.0f, 511.5f);
        float iyf = fmaf(g1, 512.0f, 511.5f);

        float fx = floorf(ixf), fy = floorf(iyf);
        int x0 = (int)fx, y0 = (int)fy;      // in [-1, 1023]
        float axx = ixf - fx, ayy = iyf - fy;
        float omx = 1.0f - axx, omy = 1.0f - ayy;

        bool interior = (x0 >= 0) & (x0 < S - 1) & (y0 >= 0) & (y0 < S - 1);
        if (__all_sync(0xffffffffu, interior)) {
            wgt[p][0] = omy * omx;
            wgt[p][1] = omy * axx;
            wgt[p][2] = ayy * omx;
            wgt[p][3] = ayy * axx;
            int o00 = (y0 << 10) + x0;
            off[p][0] = o00;
            off[p][1] = o00 + 1;
            off[p][2] = o00 + S;
            off[p][3] = o00 + S + 1;
        } else {
            float mx0 = (x0 >= 0)    ? 1.0f : 0.0f;
            float mx1 = (x0 < S - 1) ? 1.0f : 0.0f;
            float wy0 = (y0 >= 0)    ? omy  : 0.0f;
            float wy1 = (y0 < S - 1) ? ayy  : 0.0f;
            wgt[p][0] = wy0 * omx * mx0;
            wgt[p][1] = wy0 * axx * mx1;
            wgt[p][2] = wy1 * omx * mx0;
            wgt[p][3] = wy1 * axx * mx1;
            int xc0 = max(x0, 0);
            int xc1 = min(x0 + 1, S - 1);
            int yc0 = max(y0, 0) << 10;
            int yc1 = min(y0 + 1, S - 1) << 10;
            off[p][0] = yc0 + xc0; off[p][1] = yc0 + xc1;
            off[p][2] = yc1 + xc0; off[p][3] = yc1 + xc1;
        }
    }

    // ---- Phase 2: per channel, batch 16 loads then accumulate ----
    float r[CC][PX];

    #pragma unroll
    for (int c = 0; c < CC; c++) {
        const float* im = img + (size_t)c * S * S;
        float v[PX][4];
        #pragma unroll
        for (int p = 0; p < PX; p++) {
            #pragma unroll
            for (int k = 0; k < 4; k++)
                v[p][k] = __ldg(im + off[p][k]);
        }
        #pragma unroll
        for (int p = 0; p < PX; p++) {
            float acc = wgt[p][0] * v[p][0];
            acc = fmaf(wgt[p][1], v[p][1], acc);
            acc = fmaf(wgt[p][2], v[p][2], acc);
            acc = fmaf(wgt[p][3], v[p][3], acc);
            r[c][p] = acc;
        }
    }

    // Coalesced stores: 128B warp footprint per store instruction.
    #pragma unroll
    for (int c = 0; c < CC; c++) {
        float* oc = op + (size_t)c * S * S;
        #pragma unroll
        for (int p = 0; p < PX; p++)
            oc[p * TPB] = r[c][p];
    }
}

extern "C" void kernel_launch(void* const* d_in, const int* in_sizes, int n_in,
                              void* d_out, int out_size)
{
    const float* x  = (const float*)d_in[0];
    const float* ox = (const float*)d_in[1];
    const float* oy = (const float*)d_in[2];
    const float* w  = (const float*)d_in[3];
    const int*   mm = (const int*)  d_in[4];

    smooth_kernel<<<BB * 2, 128>>>(ox, oy, w, mm);

    dim3 blk(TPB, 1, 1);
    dim3 grd(S / SPAN, S, BB);   // 2 x 1024 x 8
    deform_kernel<<<grd, blk>>>(x, (float*)d_out);
}

// round 12
// speedup vs baseline: 1.1642x; 1.1642x over previous
#include <cuda_runtime.h>

#define S 1024
#define G 10
#define F 5
#define BB 8
#define CC 3
#define KW (2*F+1)
#define TPB 128       // threads per block = columns per tile
#define RY 8          // rows per block (y-locality)

// Scratch for the smoothed, clipped offset field: (B, 2, G, G)
__device__ float g_smooth_dev[BB * 2 * G * G];

// ---------------------------------------------------------------------------
// Kernel 1: 11x11 edge-padded conv of the 10x10 offset fields + clip.
// ---------------------------------------------------------------------------
__global__ void smooth_kernel(const float* __restrict__ ox,
                              const float* __restrict__ oy,
                              const float* __restrict__ w,
                              const int*   __restrict__ mm_raw)
{
    int   mi = mm_raw[0];
    float max_move = (mi > 0 && mi < 1000000) ? (float)mi : __int_as_float(mi);
    float max_offset = 2.0f * max_move / (float)S;

    __shared__ float sw[KW * KW];
    __shared__ float so[G * G];

    int b  = blockIdx.x >> 1;
    int ch = blockIdx.x & 1;
    const float* o = (ch == 0 ? ox : oy) + b * G * G;

    for (int i = threadIdx.x; i < KW * KW; i += blockDim.x) sw[i] = w[i];
    for (int i = threadIdx.x; i < G * G;   i += blockDim.x) so[i] = o[i];
    __syncthreads();

    for (int idx = threadIdx.x; idx < G * G; idx += blockDim.x) {
        int i = idx / G, j = idx % G;
        float acc = 0.0f;
        #pragma unroll
        for (int ky = 0; ky < KW; ky++) {
            int yy = min(max(i + ky - F, 0), G - 1);
            #pragma unroll
            for (int kx = 0; kx < KW; kx++) {
                int xx = min(max(j + kx - F, 0), G - 1);
                acc += so[yy * G + xx] * sw[ky * KW + kx];
            }
        }
        acc *= max_offset;
        acc = fminf(fmaxf(acc, -max_offset), max_offset);
        g_smooth_dev[(b * 2 + ch) * G * G + idx] = acc;
    }
}

// ---------------------------------------------------------------------------
// Kernel 2: 2-D tiled grid sample. Block = 128 cols x 8 rows; thread = one
// column, 8 consecutive rows. Adjacent rows' bilinear corners mostly alias
// (smooth field), so ~half the gather LDGs hit L1 instead of L2.
// Field x-lerp coords hoisted (column-invariant across rows).
// <=32 regs forced for 64-warp occupancy.
// ---------------------------------------------------------------------------
__global__ __launch_bounds__(TPB, 16)
void deform_kernel(const float* __restrict__ x, float* __restrict__ out)
{
    const int b     = blockIdx.z;
    const int ybase = blockIdx.y * RY;
    const int col   = blockIdx.x * TPB + threadIdx.x;
    const int tid   = threadIdx.x;

    __shared__ float rowg[RY][2 * G];   // y-lerped field rows for this tile

    const float scale = (float)G / (float)S;      // exact
    const float hs    = 0.5f * scale - 0.5f;

    // Prologue: y-lerp the smoothed field for all RY rows of this tile.
    for (int i = tid; i < RY * 2 * G; i += TPB) {
        int r  = i / (2 * G);
        int t  = i - r * (2 * G);
        int ch = t / G;
        int j  = t - ch * G;
        float sy  = fmaxf(fmaf((float)(ybase + r), scale, hs), 0.0f);
        int   iy0 = min((int)sy, G - 1);
        int   iy1 = min(iy0 + 1, G - 1);
        float wy  = sy - (float)iy0;
        const float* f = g_smooth_dev + (b * 2 + ch) * G * G;
        float a = f[iy0 * G + j];
        float c = f[iy1 * G + j];
        rowg[r][t] = fmaf(c - a, wy, a);
    }
    __syncthreads();

    // Column-invariant field x-lerp coordinates (hoisted out of row loop)
    const float pxs = 2.0f / (float)(S - 1);
    float sx = fmaxf(fmaf((float)col, scale, hs), 0.0f);
    int   j0 = min((int)sx, G - 1);
    int   j1 = min(j0 + 1, G - 1);
    float wx = sx - (float)j0;
    const float pxv = fmaf((float)col, pxs, -1.0f);   // identity grid x

    const float* img = x   + (size_t)b * CC * S * S;
    float*       op  = out + (size_t)b * CC * S * S + (size_t)ybase * S + col;

    for (int r = 0; r < RY; r++) {
        // field lerp for this row
        float ax0 = rowg[r][j0],     ax1 = rowg[r][j1];
        float ay0 = rowg[r][G + j0], ay1 = rowg[r][G + j1];
        float gx = fmaf(ax1 - ax0, wx, ax0);
        float gy = fmaf(ay1 - ay0, wx, ay0);

        // identity grid + clip
        float g0 = fminf(fmaxf(gx + pxv, -1.0f), 1.0f);
        float g1 = fminf(fmaxf(gy + fmaf((float)(ybase + r), pxs, -1.0f), -1.0f), 1.0f);

        // source coords: g*512 + 511.5, in [-0.5, 1023.5]
        float ixf = fmaf(g0, 512.0f, 511.5f);
        float iyf = fmaf(g1, 512.0f, 511.5f);

        float fx = floorf(ixf), fy = floorf(iyf);
        int x0 = (int)fx, y0 = (int)fy;      // in [-1, 1023]
        float axx = ixf - fx, ayy = iyf - fy;
        float omx = 1.0f - axx, omy = 1.0f - ayy;

        float w00, w01, w10, w11;
        int   o00, o01, o10, o11;

        bool interior = (x0 >= 0) & (x0 < S - 1) & (y0 >= 0) & (y0 < S - 1);
        if (__all_sync(0xffffffffu, interior)) {
            w00 = omy * omx;
            w01 = omy * axx;
            w10 = ayy * omx;
            w11 = ayy * axx;
            o00 = (y0 << 10) + x0;
            o01 = o00 + 1;
            o10 = o00 + S;
            o11 = o10 + 1;
        } else {
            float mx0 = (x0 >= 0)    ? 1.0f : 0.0f;
            float mx1 = (x0 < S - 1) ? 1.0f : 0.0f;
            float wy0 = (y0 >= 0)    ? omy  : 0.0f;
            float wy1 = (y0 < S - 1) ? ayy  : 0.0f;
            w00 = wy0 * omx * mx0;
            w01 = wy0 * axx * mx1;
            w10 = wy1 * omx * mx0;
            w11 = wy1 * axx * mx1;
            int xc0 = max(x0, 0);
            int xc1 = min(x0 + 1, S - 1);
            int yc0 = max(y0, 0) << 10;
            int yc1 = min(y0 + 1, S - 1) << 10;
            o00 = yc0 + xc0; o01 = yc0 + xc1;
            o10 = yc1 + xc0; o11 = yc1 + xc1;
        }

        float* oc = op + (size_t)r * S;
        #pragma unroll
        for (int c = 0; c < CC; c++) {
            const float* im = img + (size_t)c * S * S;
            float v = w00 * __ldg(im + o00) + w01 * __ldg(im + o01)
                    + w10 * __ldg(im + o10) + w11 * __ldg(im + o11);
            oc[(size_t)c * S * S] = v;
        }
    }
}

extern "C" void kernel_launch(void* const* d_in, const int* in_sizes, int n_in,
                              void* d_out, int out_size)
{
    const float* x  = (const float*)d_in[0];
    const float* ox = (const float*)d_in[1];
    const float* oy = (const float*)d_in[2];
    const float* w  = (const float*)d_in[3];
    const int*   mm = (const int*)  d_in[4];

    smooth_kernel<<<BB * 2, 128>>>(ox, oy, w, mm);

    dim3 blk(TPB, 1, 1);
    dim3 grd(S / TPB, S / RY, BB);   // 8 x 128 x 8 = 8192 blocks
    deform_kernel<<<grd, blk>>>(x, (float*)d_out);
}